// round 4
// baseline (speedup 1.0000x reference)
#include <cuda_runtime.h>
#include <cuda_fp16.h>
#include <math_constants.h>

#define D 512
#define STEPS 6
#define NB 148
#define NT 512
#define NW 16
#define TW (NB * NW)
#define MAXN 100000

typedef unsigned long long u64;

// ---- device scratch (static; no allocations) ----
__device__ __align__(16) uint4 g_xh[MAXN * 64];     // fp16 copy of x (102.4 MB)
__device__ __align__(16) float g_ps[NB * D];
__device__ __align__(16) float g_pm[NB];
__device__ __align__(16) float g_pz[NB];
__device__ __align__(16) float g_ctx[STEPS * D];
__device__ __align__(16) float g_gates[4 * D];
__device__ __align__(16) float g_y[D];
__device__ volatile unsigned g_cnt[32];             // monotonic barrier counters

// ---- f32x2 packed helpers ----
__device__ __forceinline__ u64 fma2(u64 a, u64 b, u64 c) {
    u64 d; asm("fma.rn.f32x2 %0, %1, %2, %3;" : "=l"(d) : "l"(a), "l"(b), "l"(c)); return d;
}
__device__ __forceinline__ u64 mul2(u64 a, u64 b) {
    u64 d; asm("mul.rn.f32x2 %0, %1, %2;" : "=l"(d) : "l"(a), "l"(b)); return d;
}
__device__ __forceinline__ u64 add2(u64 a, u64 b) {
    u64 d; asm("add.rn.f32x2 %0, %1, %2;" : "=l"(d) : "l"(a), "l"(b)); return d;
}
__device__ __forceinline__ u64 bcast2(float v) {
    u64 d; asm("mov.b64 %0, {%1, %1};" : "=l"(d) : "f"(v)); return d;
}
__device__ __forceinline__ u64 pack2(float a, float b) {
    u64 d; asm("mov.b64 %0, {%1, %2};" : "=l"(d) : "f"(a), "f"(b)); return d;
}
__device__ __forceinline__ void unpack2(u64 v, float& a, float& b) {
    asm("mov.b64 {%0, %1}, %2;" : "=f"(a), "=f"(b) : "l"(v));
}
__device__ __forceinline__ u64 h2tof2(unsigned hh) {
    __half2 h = *reinterpret_cast<__half2*>(&hh);
    float2 f = __half22float2(h);
    return pack2(f.x, f.y);
}
__device__ __forceinline__ unsigned f2toh2(float a, float b) {
    __half2 h = __floats2half2_rn(a, b);
    return *reinterpret_cast<unsigned*>(&h);
}

__device__ __forceinline__ float warp_sum(float v) {
#pragma unroll
    for (int o = 16; o; o >>= 1) v += __shfl_xor_sync(0xffffffffu, v, o);
    return v;
}

// Grid barrier: monotonic epoch counters -> replay-safe.
__device__ __forceinline__ void gbar(int k) {
    __syncthreads();
    if (threadIdx.x == 0) {
        __threadfence();
        unsigned prev = atomicAdd((unsigned*)(g_cnt + k), 1u);
        unsigned target = (prev / gridDim.x + 1u) * gridDim.x;
        while (g_cnt[k] < target) __nanosleep(64);
        __threadfence();
    }
    __syncthreads();
}

__device__ __forceinline__ float dot2(const u64* v, const u64* hq) {
    u64 d0 = mul2(v[0], hq[0]);
    u64 d1 = mul2(v[1], hq[1]);
    d0 = fma2(v[2], hq[2], d0);
    d1 = fma2(v[3], hq[3], d1);
    d0 = fma2(v[4], hq[4], d0);
    d1 = fma2(v[5], hq[5], d1);
    d0 = fma2(v[6], hq[6], d0);
    d1 = fma2(v[7], hq[7], d1);
    float a, b;
    unpack2(add2(d0, d1), a, b);
    return a + b;
}

// paired warp reduction: two partials -> both sums broadcast
__device__ __forceinline__ void reduce2(float p0, float p1, int lane,
                                        float& s0, float& s1) {
    const bool odd = lane & 1;
    float give = odd ? p0 : p1;
    float keep = odd ? p1 : p0;
    keep += __shfl_xor_sync(0xffffffffu, give, 1);
    keep += __shfl_xor_sync(0xffffffffu, keep, 2);
    keep += __shfl_xor_sync(0xffffffffu, keep, 4);
    keep += __shfl_xor_sync(0xffffffffu, keep, 8);
    keep += __shfl_xor_sync(0xffffffffu, keep, 16);
    s0 = __shfl_sync(0xffffffffu, keep, 0);
    s1 = __shfl_sync(0xffffffffu, keep, 1);
}

__global__ __launch_bounds__(NT, 1) void s2sK(const float* __restrict__ x,
                                              const float* __restrict__ W_ih,
                                              const float* __restrict__ W_hh,
                                              const float* __restrict__ b_ih,
                                              const float* __restrict__ b_hh,
                                              const float* __restrict__ W_proj,
                                              const float* __restrict__ b_proj,
                                              float* __restrict__ out,
                                              int N) {
    __shared__ __align__(16) float s_big[NW * D];    // 32 KB
    __shared__ __align__(16) float s_h[D];
    __shared__ __align__(16) float s_c[D];
    __shared__ __align__(16) float s_ctx[D];
    __shared__ float s_m[NW], s_z[NW];
    __shared__ float s_w[NB];

    const int t    = threadIdx.x;
    const int wi   = t >> 5;
    const int lane = t & 31;
    const int b    = blockIdx.x;
    int bk = 0;

    s_h[t] = 0.f;
    s_c[t] = 0.f;
    __syncthreads();

    for (int s = 0; s < STEPS; s++) {
        float m, Z;
        u64 acc[8];
#pragma unroll
        for (int i = 0; i < 8; i++) acc[i] = 0ull;

        if (s == 0) {
            // ===== Step 0: h == 0 -> uniform weights -> plain mean of x.
            // Also emit the fp16 copy of x for steps 1..5.
            const float4* __restrict__ x4 = (const float4*)x;
            int r = b * NW + wi;
            int cnt = 0;
            float4 cur[4];
            if (r < N) {
                const float4* row = x4 + (size_t)r * 128 + lane;
#pragma unroll
                for (int i = 0; i < 4; i++)
                    cur[i] = __ldcs(row + i * 32);    // evict-first: protect fp16 copy
            }
            for (; r < N; r += TW) {
                float4 nx[4];
                const int rn = r + TW;
                if (rn < N) {
                    const float4* row = x4 + (size_t)rn * 128 + lane;
#pragma unroll
                    for (int i = 0; i < 4; i++) nx[i] = __ldcs(row + i * 32);
                }
                // accumulate mean
#pragma unroll
                for (int i = 0; i < 4; i++) {
                    acc[2 * i]     = add2(acc[2 * i],     pack2(cur[i].x, cur[i].y));
                    acc[2 * i + 1] = add2(acc[2 * i + 1], pack2(cur[i].z, cur[i].w));
                }
                cnt++;
                // fp16 copy: 2 uint4 per lane per row
                uint4 u0, u1;
                u0.x = f2toh2(cur[0].x, cur[0].y);  u0.y = f2toh2(cur[0].z, cur[0].w);
                u0.z = f2toh2(cur[1].x, cur[1].y);  u0.w = f2toh2(cur[1].z, cur[1].w);
                u1.x = f2toh2(cur[2].x, cur[2].y);  u1.y = f2toh2(cur[2].z, cur[2].w);
                u1.z = f2toh2(cur[3].x, cur[3].y);  u1.w = f2toh2(cur[3].z, cur[3].w);
                uint4* dst = g_xh + (size_t)r * 64 + lane;
                dst[0]  = u0;
                dst[32] = u1;
#pragma unroll
                for (int i = 0; i < 4; i++) cur[i] = nx[i];
            }
            m = 0.f;
            Z = (float)cnt;
        } else {
            // ===== Steps 1..5: fused attention over L2-resident fp16 copy =====
            const bool fwd = !(s & 1);   // serpentine (step 1 backward -> hits step-0 tail)
            const ulonglong2* h2 = (const ulonglong2*)s_h;
            u64 hq[8];
#pragma unroll
            for (int i = 0; i < 4; i++) {
                ulonglong2 q = h2[i * 32 + lane];
                hq[2 * i] = q.x; hq[2 * i + 1] = q.y;
            }
            m = -CUDART_INF_F;
            Z = 0.f;

            uint4 A0[2], A1[2], B0[2], B1[2];
#pragma unroll
            for (int i = 0; i < 2; i++) {
                A0[i] = make_uint4(0, 0, 0, 0); A1[i] = make_uint4(0, 0, 0, 0);
                B0[i] = make_uint4(0, 0, 0, 0); B1[i] = make_uint4(0, 0, 0, 0);
            }

            auto ldrow = [&](uint4* v, int rr) {
                if (rr < N) {
                    const long long phys = fwd ? rr : (N - 1 - rr);
                    const uint4* p = g_xh + phys * 64 + lane;
                    v[0] = p[0];
                    v[1] = p[32];
                }
            };
            auto conv = [&](const uint4* raw, u64* f) {
                f[0] = h2tof2(raw[0].x); f[1] = h2tof2(raw[0].y);
                f[2] = h2tof2(raw[0].z); f[3] = h2tof2(raw[0].w);
                f[4] = h2tof2(raw[1].x); f[5] = h2tof2(raw[1].y);
                f[6] = h2tof2(raw[1].z); f[7] = h2tof2(raw[1].w);
            };
            auto step2 = [&](const uint4* r0, const uint4* r1, int idx1) {
                u64 v0[8], v1[8];
                conv(r0, v0);
                conv(r1, v1);
                float p0 = dot2(v0, hq);
                float p1 = dot2(v1, hq);
                if (idx1 >= N) p1 = -CUDART_INF_F;   // warp-uniform
                float s0, s1;
                reduce2(p0, p1, lane, s0, s1);
                const float pm = fmaxf(s0, s1);
                if (pm > m) {
                    const float sc = __expf(m - pm);
                    m = pm;
                    Z *= sc;
                    const u64 sc2 = bcast2(sc);
#pragma unroll
                    for (int i = 0; i < 8; i++) acc[i] = mul2(acc[i], sc2);
                }
                const float e0 = __expf(s0 - m);
                const float e1 = __expf(s1 - m);
                Z += e0 + e1;
                const u64 e02 = bcast2(e0);
                const u64 e12 = bcast2(e1);
#pragma unroll
                for (int i = 0; i < 8; i++) acc[i] = fma2(v0[i], e02, acc[i]);
#pragma unroll
                for (int i = 0; i < 8; i++) acc[i] = fma2(v1[i], e12, acc[i]);
            };

            int rr = b * NW + wi;
            ldrow(A0, rr); ldrow(A1, rr + TW);
            while (rr < N) {
                int rn = rr + 2 * TW;
                ldrow(B0, rn); ldrow(B1, rn + TW);
                step2(A0, A1, rr + TW);
                rr = rn;
                if (rr >= N) break;
                rn = rr + 2 * TW;
                ldrow(A0, rn); ldrow(A1, rn + TW);
                step2(B0, B1, rr + TW);
                rr = rn;
            }
        }

        // ===== shared block-combine of 16 warp partials =====
        if (lane == 0) { s_m[wi] = m; s_z[wi] = Z; }
        __syncthreads();
        {
            float mb = -CUDART_INF_F;
#pragma unroll
            for (int w = 0; w < NW; w++) mb = fmaxf(mb, s_m[w]);
            const float sc = __expf(m - mb);
            float4* dst = (float4*)&s_big[wi * D];
#pragma unroll
            for (int i = 0; i < 4; i++) {
                float x0, x1, x2f, x3;
                unpack2(acc[2 * i], x0, x1);
                unpack2(acc[2 * i + 1], x2f, x3);
                dst[i * 32 + lane] = make_float4(x0 * sc, x1 * sc, x2f * sc, x3 * sc);
            }
            __syncthreads();
            {
                float ss = 0.f;
#pragma unroll
                for (int w = 0; w < NW; w++) ss += s_big[w * D + t];
                __stcg(&g_ps[b * D + t], ss);
            }
            if (t == 0) {
                float zb = 0.f;
                for (int w = 0; w < NW; w++) zb += s_z[w] * __expf(s_m[w] - mb);
                __stcg(&g_pm[b], mb);
                __stcg(&g_pz[b], zb);
            }
        }
        gbar(bk++);

        // ===== Phase B: combine partials -> ctx (blocks 0..7) =====
        if (b < 8) {
            float lm = (t < NB) ? __ldcg(&g_pm[t]) : -CUDART_INF_F;
            s_big[t] = lm;
            __syncthreads();
            for (int o = 256; o; o >>= 1) {
                if (t < o) s_big[t] = fmaxf(s_big[t], s_big[t + o]);
                __syncthreads();
            }
            const float M = s_big[0];
            __syncthreads();
            float zz = 0.f;
            if (t < NB) {
                const float w = __expf(__ldcg(&g_pm[t]) - M);
                s_w[t] = w;
                zz = w * __ldcg(&g_pz[t]);
            }
            s_big[t] = zz;
            __syncthreads();
            for (int o = 256; o; o >>= 1) {
                if (t < o) s_big[t] += s_big[t + o];
                __syncthreads();
            }
            const float Zs = s_big[0];
            __syncthreads();

            const int dim = t & 63, c = t >> 6;
            const int gd = b * 64 + dim;
            float a = 0.f;
#pragma unroll 4
            for (int q = c; q < NB; q += 8) a += __ldcg(&g_ps[q * D + gd]) * s_w[q];
            s_big[c * 64 + dim] = a;
            __syncthreads();
            if (t < 64) {
                float ssum = 0.f;
#pragma unroll
                for (int c2 = 0; c2 < 8; c2++) ssum += s_big[c2 * 64 + t];
                __stcg(&g_ctx[s * D + b * 64 + t], ssum / Zs);
            }
        }
        gbar(bk++);

        if (s == STEPS - 1) break;   // last LSTM update unused

        // ===== Phase C: gate rows (warp per row) =====
        for (int i = t; i < D; i += NT) s_ctx[i] = __ldcg(&g_ctx[s * D + i]);
        __syncthreads();
        {
            const int row = b + NB * wi;
            if (row < 4 * D) {
                const float4* wr = (const float4*)(W_ih + (size_t)row * (2 * D));
                const float4* ur = (const float4*)(W_hh + (size_t)row * D);
                const float4* c4 = (const float4*)s_ctx;
                const float4* h4 = (const float4*)s_h;
                float a = 0.f;
#pragma unroll
                for (int i = 0; i < 4; i++) {
                    const float4 w = wr[i * 32 + lane], v = c4[i * 32 + lane];
                    a += w.x * v.x + w.y * v.y + w.z * v.z + w.w * v.w;
                }
#pragma unroll
                for (int i = 0; i < 4; i++) {
                    const float4 w = wr[(i + 4) * 32 + lane], v = h4[i * 32 + lane];
                    a += w.x * v.x + w.y * v.y + w.z * v.z + w.w * v.w;
                }
#pragma unroll
                for (int i = 0; i < 4; i++) {
                    const float4 w = ur[i * 32 + lane], v = h4[i * 32 + lane];
                    a += w.x * v.x + w.y * v.y + w.z * v.z + w.w * v.w;
                }
                a = warp_sum(a);
                if (lane == 0) __stcg(&g_gates[row], a);
            }
        }
        gbar(bk++);

        // LSTM pointwise (redundant per block; h/c in smem)
        {
            const int j = t;
            float gi = __ldcg(&g_gates[j])         + b_ih[j]         + b_hh[j];
            float gf = __ldcg(&g_gates[D + j])     + b_ih[D + j]     + b_hh[D + j];
            float gg = __ldcg(&g_gates[2 * D + j]) + b_ih[2 * D + j] + b_hh[2 * D + j];
            float go = __ldcg(&g_gates[3 * D + j]) + b_ih[3 * D + j] + b_hh[3 * D + j];
            gi = 1.f / (1.f + __expf(-gi));
            gf = 1.f / (1.f + __expf(-gf));
            gg = tanhf(gg);
            go = 1.f / (1.f + __expf(-go));
            const float cn = gf * s_c[j] + gi * gg;
            s_c[j] = cn;
            s_h[j] = go * tanhf(cn);
        }
        __syncthreads();
    }

    // ===== Projection: warp per output row =====
    for (int i = t; i < STEPS * D; i += NT) s_big[i] = __ldcg(&g_ctx[i]);
    __syncthreads();
    {
        const int row = b + NB * wi;
        if (row < D) {
            const float4* wr = (const float4*)(W_proj + (size_t)row * (STEPS * D));
            const float4* c4 = (const float4*)s_big;
            float a = 0.f;
#pragma unroll
            for (int i = 0; i < 24; i++) {
                const float4 w = wr[i * 32 + lane], v = c4[i * 32 + lane];
                a += w.x * v.x + w.y * v.y + w.z * v.z + w.w * v.w;
            }
            a = warp_sum(a);
            if (lane == 0) __stcg(&g_y[row], a + b_proj[row]);
        }
    }
    gbar(bk++);

    // ===== Final softmax (block 0) =====
    if (b == 0) {
        const float v = __ldcg(&g_y[t]);
        s_big[t] = v;
        __syncthreads();
        for (int o = 256; o; o >>= 1) {
            if (t < o) s_big[t] = fmaxf(s_big[t], s_big[t + o]);
            __syncthreads();
        }
        const float M = s_big[0];
        __syncthreads();
        const float e = __expf(v - M);
        s_big[t] = e;
        __syncthreads();
        for (int o = 256; o; o >>= 1) {
            if (t < o) s_big[t] += s_big[t + o];
            __syncthreads();
        }
        out[t] = e / s_big[0];
    }
}

extern "C" void kernel_launch(void* const* d_in, const int* in_sizes, int n_in,
                              void* d_out, int out_size) {
    const float* x      = (const float*)d_in[0];
    const float* W_ih   = (const float*)d_in[1];
    const float* W_hh   = (const float*)d_in[2];
    const float* b_ih   = (const float*)d_in[3];
    const float* b_hh   = (const float*)d_in[4];
    const float* W_proj = (const float*)d_in[5];
    const float* b_proj = (const float*)d_in[6];
    float* out = (float*)d_out;
    const int N = in_sizes[0] / D;

    s2sK<<<NB, NT>>>(x, W_ih, W_hh, b_ih, b_hh, W_proj, b_proj, out, N);
}

// round 5
// speedup vs baseline: 1.6474x; 1.6474x over previous
#include <cuda_runtime.h>
#include <cuda_fp16.h>
#include <math_constants.h>

#define D 512
#define STEPS 6
#define NB 148
#define NT 512
#define NW 16
#define TW (NB * NW)
#define MAXN 100000

typedef unsigned long long u64;

// ---- device scratch (static; no allocations) ----
__device__ __align__(16) uint4 g_xh[MAXN * 64];     // fp16 copy of x (102.4 MB)
__device__ __align__(16) float g_ps[NB * D];
__device__ __align__(16) float g_pm[NB];
__device__ __align__(16) float g_pz[NB];
__device__ __align__(16) float g_ctx[STEPS * D];
__device__ __align__(16) float g_gates[4 * D];
__device__ __align__(16) float g_y[D];
__device__ volatile unsigned g_cnt[32];             // monotonic barrier counters

// ---- f32x2 packed helpers ----
__device__ __forceinline__ u64 fma2(u64 a, u64 b, u64 c) {
    u64 d; asm("fma.rn.f32x2 %0, %1, %2, %3;" : "=l"(d) : "l"(a), "l"(b), "l"(c)); return d;
}
__device__ __forceinline__ u64 mul2(u64 a, u64 b) {
    u64 d; asm("mul.rn.f32x2 %0, %1, %2;" : "=l"(d) : "l"(a), "l"(b)); return d;
}
__device__ __forceinline__ u64 add2(u64 a, u64 b) {
    u64 d; asm("add.rn.f32x2 %0, %1, %2;" : "=l"(d) : "l"(a), "l"(b)); return d;
}
__device__ __forceinline__ u64 bcast2(float v) {
    u64 d; asm("mov.b64 %0, {%1, %1};" : "=l"(d) : "f"(v)); return d;
}
__device__ __forceinline__ u64 pack2(float a, float b) {
    u64 d; asm("mov.b64 %0, {%1, %2};" : "=l"(d) : "f"(a), "f"(b)); return d;
}
__device__ __forceinline__ void unpack2(u64 v, float& a, float& b) {
    asm("mov.b64 {%0, %1}, %2;" : "=f"(a), "=f"(b) : "l"(v));
}
__device__ __forceinline__ u64 h2tof2(unsigned hh) {
    __half2 h = *reinterpret_cast<__half2*>(&hh);
    float2 f = __half22float2(h);
    return pack2(f.x, f.y);
}
__device__ __forceinline__ unsigned f2toh2(float a, float b) {
    __half2 h = __floats2half2_rn(a, b);
    return *reinterpret_cast<unsigned*>(&h);
}

__device__ __forceinline__ float warp_sum(float v) {
#pragma unroll
    for (int o = 16; o; o >>= 1) v += __shfl_xor_sync(0xffffffffu, v, o);
    return v;
}

// Grid barrier: monotonic epoch counters -> replay-safe.
__device__ __forceinline__ void gbar(int k) {
    __syncthreads();
    if (threadIdx.x == 0) {
        __threadfence();
        unsigned prev = atomicAdd((unsigned*)(g_cnt + k), 1u);
        unsigned target = (prev / gridDim.x + 1u) * gridDim.x;
        while (g_cnt[k] < target) __nanosleep(64);
        __threadfence();
    }
    __syncthreads();
}

__device__ __forceinline__ float dot2(const u64* v, const u64* hq) {
    u64 d0 = mul2(v[0], hq[0]);
    u64 d1 = mul2(v[1], hq[1]);
    d0 = fma2(v[2], hq[2], d0);
    d1 = fma2(v[3], hq[3], d1);
    d0 = fma2(v[4], hq[4], d0);
    d1 = fma2(v[5], hq[5], d1);
    d0 = fma2(v[6], hq[6], d0);
    d1 = fma2(v[7], hq[7], d1);
    float a, b;
    unpack2(add2(d0, d1), a, b);
    return a + b;
}

// paired warp reduction: two partials -> both sums broadcast
__device__ __forceinline__ void reduce2(float p0, float p1, int lane,
                                        float& s0, float& s1) {
    const bool odd = lane & 1;
    float give = odd ? p0 : p1;
    float keep = odd ? p1 : p0;
    keep += __shfl_xor_sync(0xffffffffu, give, 1);
    keep += __shfl_xor_sync(0xffffffffu, keep, 2);
    keep += __shfl_xor_sync(0xffffffffu, keep, 4);
    keep += __shfl_xor_sync(0xffffffffu, keep, 8);
    keep += __shfl_xor_sync(0xffffffffu, keep, 16);
    s0 = __shfl_sync(0xffffffffu, keep, 0);
    s1 = __shfl_sync(0xffffffffu, keep, 1);
}

__global__ __launch_bounds__(NT, 1) void s2sK(const float* __restrict__ x,
                                              const float* __restrict__ W_ih,
                                              const float* __restrict__ W_hh,
                                              const float* __restrict__ b_ih,
                                              const float* __restrict__ b_hh,
                                              const float* __restrict__ W_proj,
                                              const float* __restrict__ b_proj,
                                              float* __restrict__ out,
                                              int N) {
    __shared__ __align__(16) float s_big[NW * D];    // 32 KB
    __shared__ __align__(16) float s_h[D];
    __shared__ __align__(16) float s_c[D];
    __shared__ __align__(16) float s_ctx[D];
    __shared__ float s_m[NW], s_z[NW];
    __shared__ float s_w[NB];

    const int t    = threadIdx.x;
    const int wi   = t >> 5;
    const int lane = t & 31;
    const int b    = blockIdx.x;
    int bk = 0;

    s_h[t] = 0.f;
    s_c[t] = 0.f;
    __syncthreads();

    for (int s = 0; s < STEPS; s++) {
        float m, Z;
        u64 acc[8];
#pragma unroll
        for (int i = 0; i < 8; i++) acc[i] = 0ull;

        if (s == 0) {
            // ===== Step 0: h == 0 -> ctx0 = mean(x). Also emit fp16 copy. =====
            // Depth-3 single-row pipeline (12 float4 loads in flight).
            const float4* __restrict__ x4 = (const float4*)x;
            int cnt = 0;

            float4 R0[4], R1[4], R2[4];
#pragma unroll
            for (int i = 0; i < 4; i++) {
                R0[i] = make_float4(0, 0, 0, 0);
                R1[i] = make_float4(0, 0, 0, 0);
                R2[i] = make_float4(0, 0, 0, 0);
            }
            auto ld0 = [&](float4* v, int r) {
                if (r < N) {
                    const float4* row = x4 + (size_t)r * 128 + lane;
#pragma unroll
                    for (int i = 0; i < 4; i++) v[i] = __ldcs(row + i * 32);
                }
            };
            auto pr0 = [&](const float4* v, int r) {
#pragma unroll
                for (int i = 0; i < 4; i++) {
                    acc[2 * i]     = add2(acc[2 * i],     pack2(v[i].x, v[i].y));
                    acc[2 * i + 1] = add2(acc[2 * i + 1], pack2(v[i].z, v[i].w));
                }
                cnt++;
                uint4 u0, u1;
                u0.x = f2toh2(v[0].x, v[0].y);  u0.y = f2toh2(v[0].z, v[0].w);
                u0.z = f2toh2(v[1].x, v[1].y);  u0.w = f2toh2(v[1].z, v[1].w);
                u1.x = f2toh2(v[2].x, v[2].y);  u1.y = f2toh2(v[2].z, v[2].w);
                u1.z = f2toh2(v[3].x, v[3].y);  u1.w = f2toh2(v[3].z, v[3].w);
                uint4* dst = g_xh + (size_t)r * 64 + lane;
                __stcg(dst, u0);
                __stcg(dst + 32, u1);
            };

            int r = b * NW + wi;
            ld0(R0, r); ld0(R1, r + TW); ld0(R2, r + 2 * TW);
            while (r < N) {
                pr0(R0, r); ld0(R0, r + 3 * TW); r += TW;
                if (r >= N) break;
                pr0(R1, r); ld0(R1, r + 3 * TW); r += TW;
                if (r >= N) break;
                pr0(R2, r); ld0(R2, r + 3 * TW); r += TW;
            }
            m = 0.f;
            Z = (float)cnt;
        } else {
            // ===== Steps 1..5: attention over fp16 copy, depth-3 pair pipeline ====
            const bool fwd = !(s & 1);   // serpentine
            const ulonglong2* h2 = (const ulonglong2*)s_h;
            u64 hq[8];
#pragma unroll
            for (int i = 0; i < 4; i++) {
                ulonglong2 q = h2[i * 32 + lane];
                hq[2 * i] = q.x; hq[2 * i + 1] = q.y;
            }
            m = -CUDART_INF_F;
            Z = 0.f;

            // 3 pair-buffers, 4 uint4 each (rowA: [0..1], rowB: [2..3])
            uint4 P0[4], P1[4], P2[4];
#pragma unroll
            for (int i = 0; i < 4; i++) {
                P0[i] = make_uint4(0, 0, 0, 0);
                P1[i] = make_uint4(0, 0, 0, 0);
                P2[i] = make_uint4(0, 0, 0, 0);
            }

            auto ldpair = [&](uint4* v, int rr) {
                if (rr < N) {
                    const long long ph = fwd ? rr : (N - 1 - rr);
                    const uint4* p = g_xh + ph * 64 + lane;
                    v[0] = __ldcg(p);
                    v[1] = __ldcg(p + 32);
                }
                const int r2 = rr + TW;
                if (r2 < N) {
                    const long long ph = fwd ? r2 : (N - 1 - r2);
                    const uint4* p = g_xh + ph * 64 + lane;
                    v[2] = __ldcg(p);
                    v[3] = __ldcg(p + 32);
                }
            };
            auto proc = [&](const uint4* raw, int rr) {
                u64 v0[8], v1[8];
                v0[0] = h2tof2(raw[0].x); v0[1] = h2tof2(raw[0].y);
                v0[2] = h2tof2(raw[0].z); v0[3] = h2tof2(raw[0].w);
                v0[4] = h2tof2(raw[1].x); v0[5] = h2tof2(raw[1].y);
                v0[6] = h2tof2(raw[1].z); v0[7] = h2tof2(raw[1].w);
                v1[0] = h2tof2(raw[2].x); v1[1] = h2tof2(raw[2].y);
                v1[2] = h2tof2(raw[2].z); v1[3] = h2tof2(raw[2].w);
                v1[4] = h2tof2(raw[3].x); v1[5] = h2tof2(raw[3].y);
                v1[6] = h2tof2(raw[3].z); v1[7] = h2tof2(raw[3].w);
                float p0 = dot2(v0, hq);
                float p1 = dot2(v1, hq);
                if (rr + TW >= N) p1 = -CUDART_INF_F;   // warp-uniform
                float s0, s1;
                reduce2(p0, p1, lane, s0, s1);
                const float pm = fmaxf(s0, s1);
                if (pm > m) {
                    const float sc = __expf(m - pm);
                    m = pm;
                    Z *= sc;
                    const u64 sc2 = bcast2(sc);
#pragma unroll
                    for (int i = 0; i < 8; i++) acc[i] = mul2(acc[i], sc2);
                }
                const float e0 = __expf(s0 - m);
                const float e1 = __expf(s1 - m);
                Z += e0 + e1;
                const u64 e02 = bcast2(e0);
                const u64 e12 = bcast2(e1);
#pragma unroll
                for (int i = 0; i < 8; i++) acc[i] = fma2(v0[i], e02, acc[i]);
#pragma unroll
                for (int i = 0; i < 8; i++) acc[i] = fma2(v1[i], e12, acc[i]);
            };

            int rr = b * NW + wi;                // pair = (rr, rr+TW), stride 2*TW
            ldpair(P0, rr);
            ldpair(P1, rr + 2 * TW);
            ldpair(P2, rr + 4 * TW);
            while (rr < N) {
                proc(P0, rr); ldpair(P0, rr + 6 * TW); rr += 2 * TW;
                if (rr >= N) break;
                proc(P1, rr); ldpair(P1, rr + 6 * TW); rr += 2 * TW;
                if (rr >= N) break;
                proc(P2, rr); ldpair(P2, rr + 6 * TW); rr += 2 * TW;
            }
        }

        // ===== block-combine of 16 warp partials =====
        if (lane == 0) { s_m[wi] = m; s_z[wi] = Z; }
        __syncthreads();
        {
            float mb = -CUDART_INF_F;
#pragma unroll
            for (int w = 0; w < NW; w++) mb = fmaxf(mb, s_m[w]);
            const float sc = __expf(m - mb);
            float4* dst = (float4*)&s_big[wi * D];
#pragma unroll
            for (int i = 0; i < 4; i++) {
                float x0, x1, x2f, x3;
                unpack2(acc[2 * i], x0, x1);
                unpack2(acc[2 * i + 1], x2f, x3);
                dst[i * 32 + lane] = make_float4(x0 * sc, x1 * sc, x2f * sc, x3 * sc);
            }
            __syncthreads();
            {
                float ss = 0.f;
#pragma unroll
                for (int w = 0; w < NW; w++) ss += s_big[w * D + t];
                __stcg(&g_ps[b * D + t], ss);
            }
            if (t == 0) {
                float zb = 0.f;
                for (int w = 0; w < NW; w++) zb += s_z[w] * __expf(s_m[w] - mb);
                __stcg(&g_pm[b], mb);
                __stcg(&g_pz[b], zb);
            }
        }
        gbar(bk++);

        // ===== Phase B: combine partials -> ctx (blocks 0..7) =====
        if (b < 8) {
            float lm = (t < NB) ? __ldcg(&g_pm[t]) : -CUDART_INF_F;
            s_big[t] = lm;
            __syncthreads();
            for (int o = 256; o; o >>= 1) {
                if (t < o) s_big[t] = fmaxf(s_big[t], s_big[t + o]);
                __syncthreads();
            }
            const float M = s_big[0];
            __syncthreads();
            float zz = 0.f;
            if (t < NB) {
                const float w = __expf(__ldcg(&g_pm[t]) - M);
                s_w[t] = w;
                zz = w * __ldcg(&g_pz[t]);
            }
            s_big[t] = zz;
            __syncthreads();
            for (int o = 256; o; o >>= 1) {
                if (t < o) s_big[t] += s_big[t + o];
                __syncthreads();
            }
            const float Zs = s_big[0];
            __syncthreads();

            const int dim = t & 63, c = t >> 6;
            const int gd = b * 64 + dim;
            float a = 0.f;
#pragma unroll 4
            for (int q = c; q < NB; q += 8) a += __ldcg(&g_ps[q * D + gd]) * s_w[q];
            s_big[c * 64 + dim] = a;
            __syncthreads();
            if (t < 64) {
                float ssum = 0.f;
#pragma unroll
                for (int c2 = 0; c2 < 8; c2++) ssum += s_big[c2 * 64 + t];
                __stcg(&g_ctx[s * D + b * 64 + t], ssum / Zs);
            }
        }
        gbar(bk++);

        if (s == STEPS - 1) break;   // last LSTM update unused

        // ===== Phase C: gate rows (warp per row) =====
        for (int i = t; i < D; i += NT) s_ctx[i] = __ldcg(&g_ctx[s * D + i]);
        __syncthreads();
        {
            const int row = b + NB * wi;
            if (row < 4 * D) {
                const float4* wr = (const float4*)(W_ih + (size_t)row * (2 * D));
                const float4* ur = (const float4*)(W_hh + (size_t)row * D);
                const float4* c4 = (const float4*)s_ctx;
                const float4* h4 = (const float4*)s_h;
                float a = 0.f;
#pragma unroll
                for (int i = 0; i < 4; i++) {
                    const float4 w = wr[i * 32 + lane], v = c4[i * 32 + lane];
                    a += w.x * v.x + w.y * v.y + w.z * v.z + w.w * v.w;
                }
#pragma unroll
                for (int i = 0; i < 4; i++) {
                    const float4 w = wr[(i + 4) * 32 + lane], v = h4[i * 32 + lane];
                    a += w.x * v.x + w.y * v.y + w.z * v.z + w.w * v.w;
                }
#pragma unroll
                for (int i = 0; i < 4; i++) {
                    const float4 w = ur[i * 32 + lane], v = h4[i * 32 + lane];
                    a += w.x * v.x + w.y * v.y + w.z * v.z + w.w * v.w;
                }
                a = warp_sum(a);
                if (lane == 0) __stcg(&g_gates[row], a);
            }
        }
        gbar(bk++);

        // LSTM pointwise (redundant per block; h/c in smem)
        {
            const int j = t;
            float gi = __ldcg(&g_gates[j])         + b_ih[j]         + b_hh[j];
            float gf = __ldcg(&g_gates[D + j])     + b_ih[D + j]     + b_hh[D + j];
            float gg = __ldcg(&g_gates[2 * D + j]) + b_ih[2 * D + j] + b_hh[2 * D + j];
            float go = __ldcg(&g_gates[3 * D + j]) + b_ih[3 * D + j] + b_hh[3 * D + j];
            gi = 1.f / (1.f + __expf(-gi));
            gf = 1.f / (1.f + __expf(-gf));
            gg = tanhf(gg);
            go = 1.f / (1.f + __expf(-go));
            const float cn = gf * s_c[j] + gi * gg;
            s_c[j] = cn;
            s_h[j] = go * tanhf(cn);
        }
        __syncthreads();
    }

    // ===== Projection: warp per output row =====
    for (int i = t; i < STEPS * D; i += NT) s_big[i] = __ldcg(&g_ctx[i]);
    __syncthreads();
    {
        const int row = b + NB * wi;
        if (row < D) {
            const float4* wr = (const float4*)(W_proj + (size_t)row * (STEPS * D));
            const float4* c4 = (const float4*)s_big;
            float a = 0.f;
#pragma unroll
            for (int i = 0; i < 24; i++) {
                const float4 w = wr[i * 32 + lane], v = c4[i * 32 + lane];
                a += w.x * v.x + w.y * v.y + w.z * v.z + w.w * v.w;
            }
            a = warp_sum(a);
            if (lane == 0) __stcg(&g_y[row], a + b_proj[row]);
        }
    }
    gbar(bk++);

    // ===== Final softmax (block 0) =====
    if (b == 0) {
        const float v = __ldcg(&g_y[t]);
        s_big[t] = v;
        __syncthreads();
        for (int o = 256; o; o >>= 1) {
            if (t < o) s_big[t] = fmaxf(s_big[t], s_big[t + o]);
            __syncthreads();
        }
        const float M = s_big[0];
        __syncthreads();
        const float e = __expf(v - M);
        s_big[t] = e;
        __syncthreads();
        for (int o = 256; o; o >>= 1) {
            if (t < o) s_big[t] += s_big[t + o];
            __syncthreads();
        }
        out[t] = e / s_big[0];
    }
}

extern "C" void kernel_launch(void* const* d_in, const int* in_sizes, int n_in,
                              void* d_out, int out_size) {
    const float* x      = (const float*)d_in[0];
    const float* W_ih   = (const float*)d_in[1];
    const float* W_hh   = (const float*)d_in[2];
    const float* b_ih   = (const float*)d_in[3];
    const float* b_hh   = (const float*)d_in[4];
    const float* W_proj = (const float*)d_in[5];
    const float* b_proj = (const float*)d_in[6];
    float* out = (float*)d_out;
    const int N = in_sizes[0] / D;

    s2sK<<<NB, NT>>>(x, W_ih, W_hh, b_ih, b_hh, W_proj, b_proj, out, N);
}